// round 17
// baseline (speedup 1.0000x reference)
#include <cuda_runtime.h>
#include <math.h>
#include <stdint.h>

#define TT   2048
#define NH   32
#define NKV  8
#define HS   128
#define FD   64
#define NB   32          // 64-token blocks
#define EPSF 1e-12f
#define SCALE 0.08838834764831845f  // 1/sqrt(128)

#define PRA 132  // row-major A tiles [64][132]
#define PRB 132  // n-major B tiles ([n][k])
#define PRV 136  // k-major B tiles ([k][n]); 136%32=8 -> conflict-free frags
#define PW  72   // k-major W tile [128][72]; 72%32=8 -> conflict-free frags
#define PT  68   // f_k^T tile [128][68]; 68%32=4 -> conflict-free A frags

// scratch (device globals: no runtime allocation allowed)
__device__ float g_fq[NH*TT*HS];          // 33.5 MB
__device__ float g_S [NH*NB*HS*HS];       // 67 MB  per-block KV states, S[f][d]
__device__ float g_z [NH*NB*HS];          // 0.5 MB per-block key sums
__device__ float g_P [NH*NB*HS*HS];       // 67 MB  prefix states, P[f][d]
__device__ float g_zp[NH*NB*HS];          // 0.5 MB per-block prefix key sums

// ---------------------------------------------------------------------------
__device__ __forceinline__ float to_tf32(float x){
  uint32_t u; asm("cvt.rna.tf32.f32 %0, %1;" : "=r"(u) : "f"(x));
  return __uint_as_float(u);
}
__device__ __forceinline__ void st_tf32_4(float* dst, float4 v){
  dst[0]=to_tf32(v.x); dst[1]=to_tf32(v.y); dst[2]=to_tf32(v.z); dst[3]=to_tf32(v.w);
}
__device__ __forceinline__ void mma_tf32(float c[4],
    uint32_t a0,uint32_t a1,uint32_t a2,uint32_t a3, uint32_t b0,uint32_t b1){
  asm volatile("mma.sync.aligned.m16n8k8.row.col.f32.tf32.tf32.f32 "
      "{%0,%1,%2,%3}, {%4,%5,%6,%7}, {%8,%9}, {%0,%1,%2,%3};"
      : "+f"(c[0]),"+f"(c[1]),"+f"(c[2]),"+f"(c[3])
      : "r"(a0),"r"(a1),"r"(a2),"r"(a3),"r"(b0),"r"(b1));
}

// ---------------------------------------------------------------------------
// Kernel 1: feature map for Q via tf32 MMA. grid (32,32), 512 thr, 3 CTAs/SM.
// 16 warps x (16x16) output tiles; softmax 4 bands/row.
// ---------------------------------------------------------------------------
__global__ void __launch_bounds__(512,3) featmap_q_kernel(
    const float* __restrict__ x, const float* __restrict__ w)
{
  extern __shared__ float sm[];
  float* sX   = sm;              // [64][132] tf32 X; later sF fp32 [64][132]
  float* sW   = sX + 64*PRA;     // [128][72] tf32 W (k-major: [d][f])
  float* sRed = sW + 128*PW;     // [1024]: mx | mn | sp | sn  (r*4+nb)

  int tile = blockIdx.x, h = blockIdx.y;
  int tid = threadIdx.x;

  for (int i=tid; i<64*32; i+=512){
    int r=i>>5, d4=(i&31)*4;
    float4 v = *(const float4*)&x[(size_t)(tile*64+r)*(NH*HS)+h*HS+d4];
    st_tf32_4(&sX[r*PRA+d4], v);
  }
  for (int i=tid; i<128*16; i+=512){
    int d=i>>4, f4=(i&15)*4;
    float4 v = *(const float4*)&w[(size_t)h*HS*FD + d*FD + f4];
    st_tf32_4(&sW[d*PW+f4], v);
  }
  __syncthreads();

  int wd=tid>>5, lane=tid&31, g=lane>>2, tg=lane&3;
  int mb=wd&3, nb=wd>>2;
  int mbase=mb*16, nbase=nb*16;

  float c[2][4];
  #pragma unroll
  for (int nt=0;nt<2;nt++)
    #pragma unroll
    for (int e=0;e<4;e++) c[nt][e]=0.f;

  #pragma unroll 4
  for (int k0=0;k0<128;k0+=8){
    uint32_t a[4], bb[2][2];
    a[0]=__float_as_uint(sX[(mbase+g)*PRA+k0+tg]);
    a[1]=__float_as_uint(sX[(mbase+g+8)*PRA+k0+tg]);
    a[2]=__float_as_uint(sX[(mbase+g)*PRA+k0+tg+4]);
    a[3]=__float_as_uint(sX[(mbase+g+8)*PRA+k0+tg+4]);
    #pragma unroll
    for (int nt=0;nt<2;nt++){
      int C=nbase+nt*8;
      bb[nt][0]=__float_as_uint(sW[(k0+tg)*PW+C+g]);
      bb[nt][1]=__float_as_uint(sW[(k0+tg+4)*PW+C+g]);
    }
    #pragma unroll
    for (int nt=0;nt<2;nt++)
      mma_tf32(c[nt], a[0],a[1],a[2],a[3], bb[nt][0],bb[nt][1]);
  }

  // ---- band max/min (4 bands per row) ----
  #pragma unroll
  for (int half=0;half<2;half++){
    int r = mbase + half*8 + g;
    float mx=-1e30f, mn=1e30f;
    #pragma unroll
    for (int nt=0;nt<2;nt++)
      #pragma unroll
      for (int e=0;e<2;e++){
        float z = c[nt][half*2+e];
        mx=fmaxf(mx,z); mn=fminf(mn,z);
      }
    mx=fmaxf(mx,__shfl_xor_sync(0xffffffffu,mx,1,4));
    mx=fmaxf(mx,__shfl_xor_sync(0xffffffffu,mx,2,4));
    mn=fminf(mn,__shfl_xor_sync(0xffffffffu,mn,1,4));
    mn=fminf(mn,__shfl_xor_sync(0xffffffffu,mn,2,4));
    if (tg==0){ sRed[r*4+nb]=mx; sRed[256+r*4+nb]=mn; }
  }
  __syncthreads();

  // ---- exps + band sums ----
  float nn[2][4];
  #pragma unroll
  for (int half=0;half<2;half++){
    int r = mbase + half*8 + g;
    float gm = fmaxf(fmaxf(sRed[r*4+0],sRed[r*4+1]),fmaxf(sRed[r*4+2],sRed[r*4+3]));
    float gn = fminf(fminf(sRed[256+r*4+0],sRed[256+r*4+1]),
                     fminf(sRed[256+r*4+2],sRed[256+r*4+3]));
    float sp=0.f, sn=0.f;
    #pragma unroll
    for (int nt=0;nt<2;nt++)
      #pragma unroll
      for (int e=0;e<2;e++){
        float z = c[nt][half*2+e];
        float p=__expf(z-gm), q=__expf(gn-z);
        c[nt][half*2+e]=p; nn[nt][half*2+e]=q;
        sp+=p; sn+=q;
      }
    sp+=__shfl_xor_sync(0xffffffffu,sp,1,4);
    sp+=__shfl_xor_sync(0xffffffffu,sp,2,4);
    sn+=__shfl_xor_sync(0xffffffffu,sn,1,4);
    sn+=__shfl_xor_sync(0xffffffffu,sn,2,4);
    if (tg==0){ sRed[512+r*4+nb]=sp; sRed[768+r*4+nb]=sn; }
  }
  __syncthreads();

  // ---- normalize + clip + write sF (overlay sX) ----
  #pragma unroll
  for (int half=0;half<2;half++){
    int r = mbase + half*8 + g;
    float rp = 1.f/(sRed[512+r*4+0]+sRed[512+r*4+1]+sRed[512+r*4+2]+sRed[512+r*4+3]);
    float rn = 1.f/(sRed[768+r*4+0]+sRed[768+r*4+1]+sRed[768+r*4+2]+sRed[768+r*4+3]);
    #pragma unroll
    for (int nt=0;nt<2;nt++){
      int f = nbase+nt*8+2*tg;
      float p0=fmaxf(c[nt][half*2+0]*rp,EPSF), p1=fmaxf(c[nt][half*2+1]*rp,EPSF);
      float q0=fmaxf(nn[nt][half*2+0]*rn,EPSF), q1=fmaxf(nn[nt][half*2+1]*rn,EPSF);
      *(float2*)&sX[r*PRA+f]      = make_float2(p0,p1);
      *(float2*)&sX[r*PRA+FD+f]   = make_float2(q0,q1);
    }
  }
  __syncthreads();

  for (int i=tid; i<64*32; i+=512){
    int t=i>>5, f4=(i&31)*4;
    *(float4*)&g_fq[((size_t)h*TT + tile*64 + t)*HS + f4] = *(const float4*)&sX[t*PRA+f4];
  }
}

// ---------------------------------------------------------------------------
// Kernel 2: FUSED feature map for K + block state via tf32 MMA. 512 thr,
// 3 CTAs/SM. S-GEMM: 2 d-half passes, 16 warps x (32x16).
// ---------------------------------------------------------------------------
__global__ void __launch_bounds__(512,3) fkstate_kernel(
    const float* __restrict__ key, const float* __restrict__ value,
    const float* __restrict__ w)
{
  extern __shared__ float sm[];
  float* sX   = sm;              // [64][132] tf32 K-tile; later sFT [128][68]
  float* sFT  = sm;
  float* sW   = sm + 8704;       // [128][72] tf32 W; later sV [64][136]
  float* sV   = sm + 8704;
  float* sRed = sm + 8704 + 9216; // [1024]

  int b = blockIdx.x, h = blockIdx.y;
  int tid = threadIdx.x;
  int kvh = h >> 2;

  for (int i=tid; i<64*32; i+=512){
    int r=i>>5, d4=(i&31)*4;
    float4 v = *(const float4*)&key[(size_t)(b*64+r)*(NKV*HS)+kvh*HS+d4];
    st_tf32_4(&sX[r*PRA+d4], v);
  }
  for (int i=tid; i<128*16; i+=512){
    int d=i>>4, f4=(i&15)*4;
    float4 v = *(const float4*)&w[(size_t)h*HS*FD + d*FD + f4];
    st_tf32_4(&sW[d*PW+f4], v);
  }
  __syncthreads();

  int wd=tid>>5, lane=tid&31, g=lane>>2, tg=lane&3;
  int mb=wd&3, nb=wd>>2;
  int mbase=mb*16, nbase=nb*16;

  float c[2][4];
  #pragma unroll
  for (int nt=0;nt<2;nt++)
    #pragma unroll
    for (int e=0;e<4;e++) c[nt][e]=0.f;

  #pragma unroll 4
  for (int k0=0;k0<128;k0+=8){
    uint32_t a[4], bb[2][2];
    a[0]=__float_as_uint(sX[(mbase+g)*PRA+k0+tg]);
    a[1]=__float_as_uint(sX[(mbase+g+8)*PRA+k0+tg]);
    a[2]=__float_as_uint(sX[(mbase+g)*PRA+k0+tg+4]);
    a[3]=__float_as_uint(sX[(mbase+g+8)*PRA+k0+tg+4]);
    #pragma unroll
    for (int nt=0;nt<2;nt++){
      int C=nbase+nt*8;
      bb[nt][0]=__float_as_uint(sW[(k0+tg)*PW+C+g]);
      bb[nt][1]=__float_as_uint(sW[(k0+tg+4)*PW+C+g]);
    }
    #pragma unroll
    for (int nt=0;nt<2;nt++)
      mma_tf32(c[nt], a[0],a[1],a[2],a[3], bb[nt][0],bb[nt][1]);
  }

  #pragma unroll
  for (int half=0;half<2;half++){
    int r = mbase + half*8 + g;
    float mx=-1e30f, mn=1e30f;
    #pragma unroll
    for (int nt=0;nt<2;nt++)
      #pragma unroll
      for (int e=0;e<2;e++){
        float z = c[nt][half*2+e];
        mx=fmaxf(mx,z); mn=fminf(mn,z);
      }
    mx=fmaxf(mx,__shfl_xor_sync(0xffffffffu,mx,1,4));
    mx=fmaxf(mx,__shfl_xor_sync(0xffffffffu,mx,2,4));
    mn=fminf(mn,__shfl_xor_sync(0xffffffffu,mn,1,4));
    mn=fminf(mn,__shfl_xor_sync(0xffffffffu,mn,2,4));
    if (tg==0){ sRed[r*4+nb]=mx; sRed[256+r*4+nb]=mn; }
  }
  __syncthreads();   // sW reads (GEMM) done -> sV overlay legal below

  float nn[2][4];
  #pragma unroll
  for (int half=0;half<2;half++){
    int r = mbase + half*8 + g;
    float gm = fmaxf(fmaxf(sRed[r*4+0],sRed[r*4+1]),fmaxf(sRed[r*4+2],sRed[r*4+3]));
    float gn = fminf(fminf(sRed[256+r*4+0],sRed[256+r*4+1]),
                     fminf(sRed[256+r*4+2],sRed[256+r*4+3]));
    float sp=0.f, sn=0.f;
    #pragma unroll
    for (int nt=0;nt<2;nt++)
      #pragma unroll
      for (int e=0;e<2;e++){
        float z = c[nt][half*2+e];
        float p=__expf(z-gm), q=__expf(gn-z);
        c[nt][half*2+e]=p; nn[nt][half*2+e]=q;
        sp+=p; sn+=q;
      }
    sp+=__shfl_xor_sync(0xffffffffu,sp,1,4);
    sp+=__shfl_xor_sync(0xffffffffu,sp,2,4);
    sn+=__shfl_xor_sync(0xffffffffu,sn,1,4);
    sn+=__shfl_xor_sync(0xffffffffu,sn,2,4);
    if (tg==0){ sRed[512+r*4+nb]=sp; sRed[768+r*4+nb]=sn; }
  }
  // V load (overlay sW, dead since GEMM) — natural [t][d], tf32, pad 136
  for (int i=tid; i<64*32; i+=512){
    int t=i>>5, d4=(i&31)*4;
    float4 v = *(const float4*)&value[(size_t)(b*64+t)*(NKV*HS)+kvh*HS+d4];
    st_tf32_4(&sV[t*PRV+d4], v);
  }
  __syncthreads();

  // normalize + clip + write f_k^T (tf32) into sFT [f][t]  (overlay sX, dead)
  #pragma unroll
  for (int half=0;half<2;half++){
    int r = mbase + half*8 + g;
    float rp = 1.f/(sRed[512+r*4+0]+sRed[512+r*4+1]+sRed[512+r*4+2]+sRed[512+r*4+3]);
    float rn = 1.f/(sRed[768+r*4+0]+sRed[768+r*4+1]+sRed[768+r*4+2]+sRed[768+r*4+3]);
    #pragma unroll
    for (int nt=0;nt<2;nt++)
      #pragma unroll
      for (int e=0;e<2;e++){
        int f = nbase+nt*8+2*tg+e;
        sFT[f*PT + r]      = to_tf32(fmaxf(c[nt][half*2+e]*rp,EPSF));
        sFT[(FD+f)*PT + r] = to_tf32(fmaxf(nn[nt][half*2+e]*rn,EPSF));
      }
  }
  __syncthreads();

  // ---- S[f][d] = f_k^T @ V : 128x128, 16 warps x (32x16), 2 d-half passes
  {
    float* Sout = g_S + ((size_t)h*NB + b)*HS*HS;
    #pragma unroll
    for (int pass=0; pass<2; ++pass){
      int nbase2 = pass*64 + nb*16;
      float cc[2][2][4];
      #pragma unroll
      for (int mt=0;mt<2;mt++)
        #pragma unroll
        for (int nt=0;nt<2;nt++)
          #pragma unroll
          for (int e=0;e<4;e++) cc[mt][nt][e]=0.f;
      #pragma unroll
      for (int k0=0;k0<64;k0+=8){
        uint32_t a[2][4], bb[2][2];
        #pragma unroll
        for (int mt=0;mt<2;mt++){
          int R = mb*32 + mt*16;
          a[mt][0]=__float_as_uint(sFT[(R+g)*PT+k0+tg]);
          a[mt][1]=__float_as_uint(sFT[(R+g+8)*PT+k0+tg]);
          a[mt][2]=__float_as_uint(sFT[(R+g)*PT+k0+tg+4]);
          a[mt][3]=__float_as_uint(sFT[(R+g+8)*PT+k0+tg+4]);
        }
        #pragma unroll
        for (int nt=0;nt<2;nt++){
          int C = nbase2+nt*8;
          bb[nt][0]=__float_as_uint(sV[(k0+tg)*PRV + C+g]);
          bb[nt][1]=__float_as_uint(sV[(k0+tg+4)*PRV + C+g]);
        }
        #pragma unroll
        for (int mt=0;mt<2;mt++)
          #pragma unroll
          for (int nt=0;nt<2;nt++)
            mma_tf32(cc[mt][nt], a[mt][0],a[mt][1],a[mt][2],a[mt][3], bb[nt][0],bb[nt][1]);
      }
      #pragma unroll
      for (int mt=0;mt<2;mt++)
        #pragma unroll
        for (int half=0;half<2;half++){
          int f = mb*32 + mt*16 + half*8 + g;
          #pragma unroll
          for (int nt=0;nt<2;nt++){
            int d = nbase2+nt*8+2*tg;
            *(float2*)&Sout[f*HS + d] =
              make_float2(cc[mt][nt][half*2+0], cc[mt][nt][half*2+1]);
          }
        }
    }
  }
  // z_b[f] = sum_t f_k[t][f]  (row sums of sFT)
  if (tid < HS){
    float z=0.f;
    #pragma unroll 4
    for (int t=0;t<64;++t) z += sFT[tid*PT+t];
    g_z[((size_t)h*NB+b)*HS + tid] = z;
  }
}

// ---------------------------------------------------------------------------
// Kernel 3: prefix over S (elementwise, layout-agnostic).
// ---------------------------------------------------------------------------
__global__ void __launch_bounds__(256) prefix_kernel()
{
  int h = blockIdx.y;
  int e = blockIdx.x*256 + threadIdx.x;  // 0..16383
  float acc = 0.f;
  for (int j = 0; j <= NB-3; ++j) {
    acc += g_S[((size_t)h*NB + j)*HS*HS + e];
    g_P[((size_t)h*NB + j+2)*HS*HS + e] = acc;
  }
  if (blockIdx.x == 0 && threadIdx.x < HS) {
    float az = 0.f;
    for (int j = 0; j <= NB-3; ++j) {
      az += g_z[((size_t)h*NB + j)*HS + threadIdx.x];
      g_zp[((size_t)h*NB + j+2)*HS + threadIdx.x] = az;
    }
  }
}

// ---------------------------------------------------------------------------
// Kernel 4: main attention via tf32 mma.sync (m16n8k8). (R15, unchanged)
// 512 thr = 16 warps, each 16x32 output tile. 106 KB smem -> 2 CTAs/SM.
// ---------------------------------------------------------------------------
__global__ void __launch_bounds__(512,2) attn_kernel(
    const float* __restrict__ query, const float* __restrict__ key,
    const float* __restrict__ value, const float* __restrict__ wfraw,
    float* __restrict__ out)
{
  extern __shared__ float sm[];
  float* sA   = sm;                 // [64][132]  tf32 Q -> probs -> fq
  float* sB   = sA + 64*PRA;        // [128][136] tf32 K(132) -> V(136) -> P(136)
  float* sRed = sB + 128*PRV;       // [512]
  float* sZp  = sRed + 512;         // [128]
  float* sLn  = sZp + 128;          // [64]

  int b = blockIdx.x, h = blockIdx.y;
  int tid = threadIdx.x;
  int kvh = h >> 2;
  float wf = 1.f/(1.f+__expf(-wfraw[h]));

  int w = tid >> 5, lane = tid & 31;
  int g = lane >> 2, tg = lane & 3;
  int mb = w & 3, nb = w >> 2;
  int mbase = mb*16, nbase = nb*32;

  if (tid < 64) sLn[tid] = 0.f;

  // ---- L1: tf32(Q), tf32(K) n-major; zp ----
  for (int i = tid; i < 64*32; i += 512) {
    int r = i >> 5, d4 = (i & 31)*4;
    float4 v = *(const float4*)&query[(size_t)(b*64+r)*(NH*HS) + h*HS + d4];
    st_tf32_4(&sA[r*PRA+d4], v);
  }
  for (int i = tid; i < 128*32; i += 512) {
    int r = i >> 5, d4 = (i & 31)*4;
    float4 v;
    if (r < 64) {
      if (b == 0) v = make_float4(0.f,0.f,0.f,0.f);
      else v = *(const float4*)&key[(size_t)((b-1)*64+r)*(NKV*HS)+kvh*HS+d4];
    } else {
      v = *(const float4*)&key[(size_t)(b*64+(r-64))*(NKV*HS)+kvh*HS+d4];
    }
    st_tf32_4(&sB[r*PRB+d4], v);
  }
  if (b >= 2 && tid < HS) sZp[tid] = g_zp[((size_t)h*NB+b)*HS+tid];
  __syncthreads();

  // ---- G1: scores = Q @ K^T ----
  float c[4][4];
  #pragma unroll
  for (int nt=0;nt<4;nt++)
    #pragma unroll
    for (int e=0;e<4;e++) c[nt][e]=0.f;

  #pragma unroll 4
  for (int k0=0;k0<128;k0+=8) {
    uint32_t a[4], bb[4][2];
    a[0]=__float_as_uint(sA[(mbase+g)*PRA+k0+tg]);
    a[1]=__float_as_uint(sA[(mbase+g+8)*PRA+k0+tg]);
    a[2]=__float_as_uint(sA[(mbase+g)*PRA+k0+tg+4]);
    a[3]=__float_as_uint(sA[(mbase+g+8)*PRA+k0+tg+4]);
    #pragma unroll
    for (int nt=0;nt<4;nt++){
      int C = nbase+nt*8;
      bb[nt][0]=__float_as_uint(sB[(C+g)*PRB+k0+tg]);
      bb[nt][1]=__float_as_uint(sB[(C+g)*PRB+k0+tg+4]);
    }
    #pragma unroll
    for (int nt=0;nt<4;nt++)
      mma_tf32(c[nt], a[0],a[1],a[2],a[3], bb[nt][0],bb[nt][1]);
  }

  // ---- softmax: band max ----
  #pragma unroll
  for (int half=0;half<2;half++) {
    int r = mbase+half*8+g;
    float mx = -1e30f;
    #pragma unroll
    for (int nt=0;nt<4;nt++)
      #pragma unroll
      for (int e=0;e<2;e++) {
        int col = nbase+nt*8+2*tg+e;
        float s = c[nt][half*2+e]*SCALE;
        c[nt][half*2+e]=s;
        bool ok = (col<64) ? (b>0) : ((col-64)<=r);
        if (ok) mx = fmaxf(mx, s);
      }
    mx = fmaxf(mx, __shfl_xor_sync(0xffffffffu, mx, 1, 4));
    mx = fmaxf(mx, __shfl_xor_sync(0xffffffffu, mx, 2, 4));
    if (tg==0) sRed[r*4+nb]=mx;
  }
  __syncthreads();

  // ---- exp + band sums; probs (tf32) -> sA; tf32(V) -> sB ----
  #pragma unroll
  for (int half=0;half<2;half++) {
    int r = mbase+half*8+g;
    float gm = fmaxf(fmaxf(sRed[r*4+0],sRed[r*4+1]),fmaxf(sRed[r*4+2],sRed[r*4+3]));
    float sum=0.f;
    #pragma unroll
    for (int nt=0;nt<4;nt++){
      int col0 = nbase+nt*8+2*tg;
      bool ok0 = (col0  <64) ? (b>0) : ((col0  -64)<=r);
      bool ok1 = (col0+1<64) ? (b>0) : ((col0+1-64)<=r);
      float p0 = ok0 ? to_tf32(wf*__expf(c[nt][half*2+0]-gm)) : 0.f;
      float p1 = ok1 ? to_tf32(wf*__expf(c[nt][half*2+1]-gm)) : 0.f;
      sum += p0+p1;
      *(float2*)&sA[r*PRA + col0] = make_float2(p0,p1);
    }
    sum += __shfl_xor_sync(0xffffffffu,sum,1,4);
    sum += __shfl_xor_sync(0xffffffffu,sum,2,4);
    if (tg==0) sRed[256 + r*4+nb]=sum;
  }
  for (int i = tid; i < 128*32; i += 512) {
    int r = i >> 5, d4 = (i & 31)*4;
    float4 v;
    if (r < 64) {
      if (b == 0) v = make_float4(0.f,0.f,0.f,0.f);
      else v = *(const float4*)&value[(size_t)((b-1)*64+r)*(NKV*HS)+kvh*HS+d4];
    } else {
      v = *(const float4*)&value[(size_t)(b*64+(r-64))*(NKV*HS)+kvh*HS+d4];
    }
    st_tf32_4(&sB[r*PRV+d4], v);
  }
  #pragma unroll
  for (int nt=0;nt<4;nt++)
    #pragma unroll
    for (int e=0;e<4;e++) c[nt][e]=0.f;
  __syncthreads();

  // ---- G2: y = P @ V ----
  #pragma unroll 4
  for (int k0=0;k0<128;k0+=8) {
    uint32_t a[4], bb[4][2];
    a[0]=__float_as_uint(sA[(mbase+g)*PRA+k0+tg]);
    a[1]=__float_as_uint(sA[(mbase+g+8)*PRA+k0+tg]);
    a[2]=__float_as_uint(sA[(mbase+g)*PRA+k0+tg+4]);
    a[3]=__float_as_uint(sA[(mbase+g+8)*PRA+k0+tg+4]);
    #pragma unroll
    for (int nt=0;nt<4;nt++){
      int C = nbase+nt*8;
      bb[nt][0]=__float_as_uint(sB[(k0+tg  )*PRV + C+g]);
      bb[nt][1]=__float_as_uint(sB[(k0+tg+4)*PRV + C+g]);
    }
    #pragma unroll
    for (int nt=0;nt<4;nt++)
      mma_tf32(c[nt], a[0],a[1],a[2],a[3], bb[nt][0],bb[nt][1]);
  }

  // ---- prefix: y += fq @ P ; sum_ln = fq . zp ----
  if (b >= 2) {
    __syncthreads();
    for (int i = tid; i < 64*32; i += 512) {
      int r = i >> 5, d4 = (i & 31)*4;
      float4 v = *(const float4*)&g_fq[((size_t)h*TT + b*64 + r)*HS + d4];
      st_tf32_4(&sA[r*PRA+d4], v);
    }
    const float* P = g_P + ((size_t)h*NB + b)*HS*HS;   // P[f][d], k-major B
    for (int i = tid; i < 128*32; i += 512) {
      int r = i >> 5, d4 = (i & 31)*4;
      float4 v = *(const float4*)&P[r*HS + d4];
      st_tf32_4(&sB[r*PRV+d4], v);
    }
    __syncthreads();

    #pragma unroll 4
    for (int k0=0;k0<128;k0+=8) {
      uint32_t a[4], bb[4][2];
      a[0]=__float_as_uint(sA[(mbase+g)*PRA+k0+tg]);
      a[1]=__float_as_uint(sA[(mbase+g+8)*PRA+k0+tg]);
      a[2]=__float_as_uint(sA[(mbase+g)*PRA+k0+tg+4]);
      a[3]=__float_as_uint(sA[(mbase+g+8)*PRA+k0+tg+4]);
      #pragma unroll
      for (int nt=0;nt<4;nt++){
        int C = nbase+nt*8;
        bb[nt][0]=__float_as_uint(sB[(k0+tg  )*PRV + C+g]);
        bb[nt][1]=__float_as_uint(sB[(k0+tg+4)*PRV + C+g]);
      }
      #pragma unroll
      for (int nt=0;nt<4;nt++)
        mma_tf32(c[nt], a[0],a[1],a[2],a[3], bb[nt][0],bb[nt][1]);
    }
    if (tid < 64) {
      float s=0.f;
      #pragma unroll 4
      for (int f=0; f<HS; ++f) s += sA[tid*PRA+f]*sZp[f];
      sLn[tid]=s;
    }
  }
  __syncthreads();

  // ---- epilogue ----
  #pragma unroll
  for (int half=0;half<2;half++) {
    int r = mbase+half*8+g;
    float ssm = sRed[256+r*4+0]+sRed[256+r*4+1]+sRed[256+r*4+2]+sRed[256+r*4+3];
    float inv = 1.f/(ssm + sLn[r]);
    #pragma unroll
    for (int nt=0;nt<4;nt++){
      int col0 = nbase+nt*8+2*tg;
      *(float2*)&out[((size_t)h*TT + b*64 + r)*HS + col0] =
        make_float2(c[nt][half*2+0]*inv, c[nt][half*2+1]*inv);
    }
  }
}

// ---------------------------------------------------------------------------
extern "C" void kernel_launch(void* const* d_in, const int* in_sizes, int n_in,
                              void* d_out, int out_size)
{
  const float* q   = (const float*)d_in[0];
  const float* k   = (const float*)d_in[1];
  const float* v   = (const float*)d_in[2];
  const float* fqw = (const float*)d_in[3];
  const float* fkw = (const float*)d_in[4];
  const float* wfr = (const float*)d_in[5];
  float* out = (float*)d_out;

  // smem: featmap_q = (64*132 + 128*72 + 1024)*4 = 74752 B -> 3 CTAs/SM
  // fkstate = (8704 + 9216 + 1024)*4 = 75776 B -> 3 CTAs/SM
  // attn = 106240 B -> 2 CTAs/SM (512 thr -> 32 warps/SM)
  cudaFuncSetAttribute(featmap_q_kernel, cudaFuncAttributeMaxDynamicSharedMemorySize, 74752);
  cudaFuncSetAttribute(fkstate_kernel,   cudaFuncAttributeMaxDynamicSharedMemorySize, 75776);
  cudaFuncSetAttribute(attn_kernel,      cudaFuncAttributeMaxDynamicSharedMemorySize, 106240);

  featmap_q_kernel<<<dim3(32,32),512,74752>>>(q, fqw);
  fkstate_kernel  <<<dim3(32,32),512,75776>>>(k, v, fkw);
  prefix_kernel   <<<dim3(64,32),256>>>();
  attn_kernel     <<<dim3(32,32),512,106240>>>(q, k, v, wfr, out);
}